// round 12
// baseline (speedup 1.0000x reference)
#include <cuda_runtime.h>
#include <cuda_fp16.h>

#define T_ 512
#define S_ 512
#define B_ 8
#define D_ 512
#define H_ 8
#define HD_ 64
#define L_ 8
#define F_ 2048

// ---------------- scratch (device globals; no runtime allocation) ----------------
__device__ float  g_x  [B_*T_*D_];      // raw tgt (B,T,D) for residual
__device__ __half g_xh [B_*T_*D_];
__device__ __half g_memh[B_*S_*D_];
__device__ __half g_qh [B_*T_*D_];
__device__ __half g_kh [B_*S_*D_];
__device__ __half g_vth[D_*B_*S_];      // v^T : [channel][b*S+j]
__device__ __half g_qlh[B_*H_*T_*(L_*HD_)];   // [z=bh][i][l*64+e]
__device__ float  g_sc [B_*H_*T_*T_];
__device__ __half g_sch[B_*H_*T_*T_];
__device__ __half g_oh [B_*T_*D_];
__device__ float  g_tmp[B_*T_*D_];
__device__ float  g_x1 [B_*T_*D_];
__device__ __half g_x1h[B_*T_*D_];
__device__ float  g_x2 [B_*T_*D_];
__device__ __half g_x2h[B_*T_*D_];
__device__ __half g_ffnh[B_*T_*F_];
__device__ __half g_wtsh[4227072];

#define WQ_OFF   0
#define WK_OFF   262144
#define WV_OFF   524288
#define WO_OFF   786432
#define WCA_OFF  1048576
#define WCAO_OFF 1835008
#define WL1_OFF  2097152
#define WL2_OFF  3145728
#define WREL_OFF 4194304

// ---------------- cp.async helpers ----------------
__device__ __forceinline__ void cp16(unsigned dst, const void* src) {
    asm volatile("cp.async.ca.shared.global [%0], [%1], 16;" :: "r"(dst), "l"(src));
}
#define CP_COMMIT() asm volatile("cp.async.commit_group;" ::: "memory")
#define CP_WAIT0()  asm volatile("cp.async.wait_group 0;" ::: "memory")
#define CP_WAIT1()  asm volatile("cp.async.wait_group 1;" ::: "memory")

// K-chunk = 32 halves; row stride 48 halves (96B) -> conflict-free LDS.64
#define TST 48
#define TROW_B 96
#define TB128 (128*TST*2)   // 12288
#define TB64  (64*TST*2)    // 6144
#define SM_J  (3*(TB128+TB128))   // 73728
#define SM_SA (2*TB128+2*TB64)    // 36864
#define SM_AV (3*(TB128+TB64))    // 55296

// stage a ROWSx32-half tile; 128 threads
template<int ROWS>
__device__ __forceinline__ void cpT(unsigned dst, const __half* __restrict__ src,
                                    int ld, int k0, int tid)
{
#pragma unroll
    for (int i = 0; i < ROWS / 32; i++) {
        int idx = tid + i * 128;
        int row = idx >> 2, seg = idx & 3;
        cp16(dst + row * TROW_B + seg * 16, src + (size_t)row * ld + k0 + seg * 8);
    }
}

// ---------------- fp16 mma warp tile: (MF*16) x (NF*8), one K=32 chunk ----------------
__device__ __forceinline__ void mma16(float* c, const unsigned* a, const unsigned* b) {
    asm volatile(
        "mma.sync.aligned.m16n8k16.row.col.f32.f16.f16.f32 "
        "{%0,%1,%2,%3}, {%4,%5,%6,%7}, {%8,%9}, {%0,%1,%2,%3};"
        : "+f"(c[0]), "+f"(c[1]), "+f"(c[2]), "+f"(c[3])
        : "r"(a[0]), "r"(a[1]), "r"(a[2]), "r"(a[3]), "r"(b[0]), "r"(b[1]));
}

// k-permuted fragments (same perm on A and B => exact dot product), LDS.64 loads.
template<int MF, int NF>
__device__ __forceinline__ void mma_tile(
    const __half* __restrict__ As, const __half* __restrict__ Ws,
    int warp_m, int warp_n, int lane, float c[MF][NF][4])
{
    int r = lane >> 2, q = lane & 3;
    const __half* Ap = As + (warp_m + r) * TST + 4 * q;
    const __half* Bp = Ws + (warp_n + r) * TST + 4 * q;
#pragma unroll
    for (int kg = 0; kg < 2; kg++) {
        int kb = kg * 16;
        unsigned a[MF][4], b[NF][2];
#pragma unroll
        for (int mf = 0; mf < MF; mf++) {
            uint2 lo = *(const uint2*)(Ap + (mf * 16) * TST + kb);
            uint2 hi = *(const uint2*)(Ap + (mf * 16 + 8) * TST + kb);
            a[mf][0] = lo.x; a[mf][1] = hi.x; a[mf][2] = lo.y; a[mf][3] = hi.y;
        }
#pragma unroll
        for (int nf = 0; nf < NF; nf++) {
            uint2 bb = *(const uint2*)(Bp + nf * 8 * TST + kb);
            b[nf][0] = bb.x; b[nf][1] = bb.y;
        }
#pragma unroll
        for (int mf = 0; mf < MF; mf++)
#pragma unroll
            for (int nf = 0; nf < NF; nf++)
                mma16(c[mf][nf], a[mf], b[nf]);
    }
}

// ---------------- jobs GEMM: CTA 128x128, 4 warps (2x2) of 64x64 ----------------
struct GJob {
    const __half* A; const __half* W;
    const float* bias; const float* res;
    float* Cf; __half* Ch;
    int lda, ldw, ldc, K, gx, biasMode, relu;
};
struct GParams { GJob j[3]; };

__global__ __launch_bounds__(128) void gemm_jobs(GParams g)
{
    extern __shared__ __half sm[];
    __half* As = sm;
    __half* Ws = sm + 3 * 128 * TST;
    const GJob J = g.j[blockIdx.z];
    int tid = threadIdx.x, w = tid >> 5, lane = tid & 31;
    int warp_m = (w >> 1) * 64, warp_n = (w & 1) * 64;
    int bx = blockIdx.x % J.gx, by = blockIdx.x / J.gx;
    int row0 = by * 128, col0 = bx * 128;
    const __half* Ab = J.A + (size_t)row0 * J.lda;
    const __half* Wb = J.W + (size_t)col0 * J.ldw;
    unsigned sA = (unsigned)__cvta_generic_to_shared(As);
    unsigned sW = (unsigned)__cvta_generic_to_shared(Ws);
    float c[4][8][4] = {};
    int nch = J.K >> 5;
#pragma unroll
    for (int s = 0; s < 2; s++) {
        cpT<128>(sA + s * TB128, Ab, J.lda, s << 5, tid);
        cpT<128>(sW + s * TB128, Wb, J.ldw, s << 5, tid);
        CP_COMMIT();
    }
    for (int ch = 0; ch < nch; ch++) {
        if (ch < nch - 1) { CP_WAIT1(); } else { CP_WAIT0(); }
        __syncthreads();
        int nx = ch + 2;
        if (nx < nch) {
            int bs = nx % 3;
            cpT<128>(sA + bs * TB128, Ab, J.lda, nx << 5, tid);
            cpT<128>(sW + bs * TB128, Wb, J.ldw, nx << 5, tid);
            CP_COMMIT();
        }
        mma_tile<4, 8>(As + (ch % 3) * 128 * TST, Ws + (ch % 3) * 128 * TST,
                       warp_m, warp_n, lane, c);
    }
    int r = lane >> 2, q = lane & 3;
#pragma unroll
    for (int mf = 0; mf < 4; mf++)
#pragma unroll
    for (int rr = 0; rr < 2; rr++) {
        int row = row0 + warp_m + mf * 16 + r + rr * 8;
        float rb = (J.biasMode == 2) ? J.bias[row] : 0.f;
#pragma unroll
        for (int nf = 0; nf < 8; nf++) {
            int col = col0 + warp_n + nf * 8 + 2 * q;
            float2 o = make_float2(c[mf][nf][2 * rr], c[mf][nf][2 * rr + 1]);
            if (J.biasMode == 1) {
                float2 bb = *(const float2*)(J.bias + col);
                o.x += bb.x; o.y += bb.y;
            } else if (J.biasMode == 2) { o.x += rb; o.y += rb; }
            if (J.res) {
                float2 rv = *(const float2*)(J.res + (size_t)row * J.ldc + col);
                o.x += rv.x; o.y += rv.y;
            }
            if (J.relu) { o.x = fmaxf(o.x, 0.f); o.y = fmaxf(o.y, 0.f); }
            if (J.Cf) *(float2*)(J.Cf + (size_t)row * J.ldc + col) = o;
            if (J.Ch) *((__half2*)(J.Ch + (size_t)row * J.ldc + col)) =
                          __floats2half2_rn(o.x, o.y);
        }
    }
}

// ---------------- batched GEMM over z (z split as z>>3, z&7) ----------------
struct GBatch {
    const __half* A; const __half* W; float* Cf; __half* Ch;
    long long Ahi, Alo, Whi, Wlo, Chi, Clo;
    int lda, ldw, ldc, K, gx; float scale;
};

__global__ __launch_bounds__(128) void gemm_batch(GBatch g)
{
    extern __shared__ __half sm[];
    __half* As = sm;
    __half* Ws = sm + 3 * 128 * TST;
    int tid = threadIdx.x, w = tid >> 5, lane = tid & 31;
    int warp_m = (w >> 1) * 64, warp_n = (w & 1) * 64;
    int bx = blockIdx.x % g.gx, by = blockIdx.x / g.gx;
    int z = blockIdx.z, zhi = z >> 3, zlo = z & 7;
    int row0 = by * 128, col0 = bx * 128;
    const __half* Ab = g.A + zhi * g.Ahi + zlo * g.Alo + (size_t)row0 * g.lda;
    const __half* Wb = g.W + zhi * g.Whi + zlo * g.Wlo + (size_t)col0 * g.ldw;
    unsigned sA = (unsigned)__cvta_generic_to_shared(As);
    unsigned sW = (unsigned)__cvta_generic_to_shared(Ws);
    float c[4][8][4] = {};
    int nch = g.K >> 5;
#pragma unroll
    for (int s = 0; s < 2; s++) {
        if (s < nch) {
            cpT<128>(sA + s * TB128, Ab, g.lda, s << 5, tid);
            cpT<128>(sW + s * TB128, Wb, g.ldw, s << 5, tid);
        }
        CP_COMMIT();
    }
    for (int ch = 0; ch < nch; ch++) {
        if (ch < nch - 1) { CP_WAIT1(); } else { CP_WAIT0(); }
        __syncthreads();
        int nx = ch + 2;
        if (nx < nch) {
            int bs = nx % 3;
            cpT<128>(sA + bs * TB128, Ab, g.lda, nx << 5, tid);
            cpT<128>(sW + bs * TB128, Wb, g.ldw, nx << 5, tid);
            CP_COMMIT();
        }
        mma_tile<4, 8>(As + (ch % 3) * 128 * TST, Ws + (ch % 3) * 128 * TST,
                       warp_m, warp_n, lane, c);
    }
    int r = lane >> 2, q = lane & 3;
    float* Cf = g.Cf ? g.Cf + zhi * g.Chi + zlo * g.Clo : nullptr;
    __half* Ch = g.Ch ? g.Ch + zhi * g.Chi + zlo * g.Clo : nullptr;
#pragma unroll
    for (int mf = 0; mf < 4; mf++)
#pragma unroll
    for (int rr = 0; rr < 2; rr++) {
        int row = row0 + warp_m + mf * 16 + r + rr * 8;
#pragma unroll
        for (int nf = 0; nf < 8; nf++) {
            int col = col0 + warp_n + nf * 8 + 2 * q;
            float2 o = make_float2(c[mf][nf][2 * rr] * g.scale,
                                   c[mf][nf][2 * rr + 1] * g.scale);
            if (Cf) *(float2*)(Cf + (size_t)row * g.ldc + col) = o;
            if (Ch) *((__half2*)(Ch + (size_t)row * g.ldc + col)) =
                        __floats2half2_rn(o.x, o.y);
        }
    }
}

// ---------------- sa scores: CTA 128x64, 4 warps of 64x32 ----------------
// ql layout [z][i][l*64+e] => A is a contiguous K=512 stream; em-weight every 2 chunks.
__global__ __launch_bounds__(128) void sa_scores_kernel(
    const __half* __restrict__ qlb, const __half* __restrict__ km,
    const float* __restrict__ em, const unsigned char* __restrict__ pad,
    float* __restrict__ sc)
{
    extern __shared__ __half sm[];
    __half* As = sm;
    __half* Ws2 = sm + 2 * 128 * TST;
    int z = blockIdx.z; int h = z & 7, b = z >> 3;
    int i0 = blockIdx.y * 128, j0 = blockIdx.x * 64;
    int tid = threadIdx.x, w = tid >> 5, lane = tid & 31;
    int warp_m = (w >> 1) * 64, warp_n = (w & 1) * 32;
    int r = lane >> 2, q = lane & 3;
    unsigned sA = (unsigned)__cvta_generic_to_shared(As);
    unsigned sW = (unsigned)__cvta_generic_to_shared(Ws2);
    const __half* Kb = km + (size_t)(b * T_ + j0) * D_ + h * HD_;
    const __half* A0 = qlb + ((size_t)z * T_ + i0) * (L_ * HD_);
    cpT<64>(sW, Kb, D_, 0, tid);
    cpT<64>(sW + TB64, Kb, D_, 32, tid);
    cpT<128>(sA, A0, L_ * HD_, 0, tid);
    CP_COMMIT();

    float acc[4][4][4] = {};
    for (int l = 0; l < L_; l++) {
        float c[4][4][4] = {};
#pragma unroll
        for (int kc = 0; kc < 2; kc++) {
            int cc = l * 2 + kc;
            CP_WAIT0();
            __syncthreads();
            if (cc < 15) {
                cpT<128>(sA + ((cc + 1) & 1) * TB128, A0, L_ * HD_, (cc + 1) << 5, tid);
                CP_COMMIT();
            }
            mma_tile<4, 4>(As + (cc & 1) * 128 * TST, Ws2 + kc * 64 * TST,
                           warp_m, warp_n, lane, c);
        }
        const float* emb = em + (size_t)(b * L_ + l) * T_ * T_;
#pragma unroll
        for (int mf = 0; mf < 4; mf++)
#pragma unroll
        for (int rr = 0; rr < 2; rr++) {
            int i = i0 + warp_m + mf * 16 + r + rr * 8;
#pragma unroll
            for (int nf = 0; nf < 4; nf++) {
                int j = j0 + warp_n + nf * 8 + 2 * q;
                float2 e = *(const float2*)(emb + (size_t)i * T_ + j);
                acc[mf][nf][2 * rr]     += e.x * c[mf][nf][2 * rr];
                acc[mf][nf][2 * rr + 1] += e.y * c[mf][nf][2 * rr + 1];
            }
        }
    }
#pragma unroll
    for (int mf = 0; mf < 4; mf++)
#pragma unroll
    for (int rr = 0; rr < 2; rr++) {
        int i = i0 + warp_m + mf * 16 + r + rr * 8;
#pragma unroll
        for (int nf = 0; nf < 4; nf++) {
            int j = j0 + warp_n + nf * 8 + 2 * q;
            const unsigned char* pp = pad + (size_t)(b * T_ + i) * T_ + j;
            float2 o;
            o.x = pp[0] ? -1e9f : acc[mf][nf][2 * rr] * 0.125f;
            o.y = pp[1] ? -1e9f : acc[mf][nf][2 * rr + 1] * 0.125f;
            *(float2*)(sc + ((size_t)z * T_ + i) * T_ + j) = o;
        }
    }
}

// ---------------- row softmax over width 512: float in -> half out ----------------
__global__ void softmax_kernel(const float* __restrict__ sc, __half* __restrict__ sch)
{
    __shared__ float red[8];
    int row = blockIdx.x;
    int tid = threadIdx.x;
    const float* p = sc + (size_t)row * 512;
    __half* ph = sch + (size_t)row * 512;
    float a0 = p[tid], a1 = p[tid + 256];
    float m = fmaxf(a0, a1);
#pragma unroll
    for (int o = 16; o; o >>= 1) m = fmaxf(m, __shfl_xor_sync(0xffffffffu, m, o));
    if ((tid & 31) == 0) red[tid >> 5] = m;
    __syncthreads();
    m = red[0];
#pragma unroll
    for (int i = 1; i < 8; i++) m = fmaxf(m, red[i]);
    float e0 = __expf(a0 - m), e1 = __expf(a1 - m);
    float s = e0 + e1;
#pragma unroll
    for (int o = 16; o; o >>= 1) s += __shfl_xor_sync(0xffffffffu, s, o);
    __syncthreads();
    if ((tid & 31) == 0) red[tid >> 5] = s;
    __syncthreads();
    s = red[0] + red[1] + red[2] + red[3] + red[4] + red[5] + red[6] + red[7];
    float inv = 1.0f / s;
    ph[tid] = __float2half_rn(e0 * inv);
    ph[tid + 256] = __float2half_rn(e1 * inv);
}

// ---------------- o = attn @ v via NT with v^T: CTA 128x64, warps 64x32 ----------------
__global__ __launch_bounds__(128) void attn_v_kernel(
    const __half* __restrict__ attn, const __half* __restrict__ vt,
    __half* __restrict__ o, int kdim)
{
    extern __shared__ __half sm[];
    __half* As = sm;
    __half* Ws = sm + 3 * 128 * TST;
    int z = blockIdx.z; int h = z & 7, b = z >> 3;
    int i0 = blockIdx.y * 128;
    int tid = threadIdx.x, w = tid >> 5, lane = tid & 31;
    int warp_m = (w >> 1) * 64, warp_n = (w & 1) * 32;
    const __half* Ab = attn + (size_t)z * T_ * kdim + (size_t)i0 * kdim;
    const __half* Wb = vt + (size_t)(h * HD_) * (B_ * kdim) + (size_t)b * kdim;
    int ldw = B_ * kdim;
    unsigned sA = (unsigned)__cvta_generic_to_shared(As);
    unsigned sW = (unsigned)__cvta_generic_to_shared(Ws);
    float c[4][4][4] = {};
    int nch = kdim >> 5;
#pragma unroll
    for (int s = 0; s < 2; s++) {
        cpT<128>(sA + s * TB128, Ab, kdim, s << 5, tid);
        cpT<64>(sW + s * TB64, Wb, ldw, s << 5, tid);
        CP_COMMIT();
    }
    for (int ch = 0; ch < nch; ch++) {
        if (ch < nch - 1) { CP_WAIT1(); } else { CP_WAIT0(); }
        __syncthreads();
        int nx = ch + 2;
        if (nx < nch) {
            int bs = nx % 3;
            cpT<128>(sA + bs * TB128, Ab, kdim, nx << 5, tid);
            cpT<64>(sW + bs * TB64, Wb, ldw, nx << 5, tid);
            CP_COMMIT();
        }
        mma_tile<4, 4>(As + (ch % 3) * 128 * TST, Ws + (ch % 3) * 64 * TST,
                       warp_m, warp_n, lane, c);
    }
    int r = lane >> 2, q = lane & 3;
    __half* Ob = o + (size_t)(b * T_ + i0) * D_ + h * HD_;
#pragma unroll
    for (int mf = 0; mf < 4; mf++)
#pragma unroll
    for (int rr = 0; rr < 2; rr++) {
        int row = warp_m + mf * 16 + r + rr * 8;
#pragma unroll
        for (int nf = 0; nf < 4; nf++) {
            int col = warp_n + nf * 8 + 2 * q;
            *((__half2*)(Ob + (size_t)row * D_ + col)) =
                __floats2half2_rn(c[mf][nf][2 * rr], c[mf][nf][2 * rr + 1]);
        }
    }
}

// ---------------- (T,B,D) -> (B,T,D) gather; raw float (optional) + half ----------------
__global__ void transpose_tb(const float* __restrict__ in, float* __restrict__ out_raw,
                             __half* __restrict__ out_h, int Tdim)
{
    int row = blockIdx.x;
    int t = row / B_, b = row - t * B_;
    float4 v = ((const float4*)(in + (size_t)(t * B_ + b) * D_))[threadIdx.x];
    size_t off = (size_t)(b * Tdim + t) * D_;
    if (out_raw) ((float4*)(out_raw + off))[threadIdx.x] = v;
    __half2* hp = (__half2*)(out_h + off + threadIdx.x * 4);
    hp[0] = __floats2half2_rn(v.x, v.y);
    hp[1] = __floats2half2_rn(v.z, v.w);
}

// ---------------- LayerNorm over D=512; raw float + optional half ----------------
__global__ void ln_kernel(const float* __restrict__ in, const float* __restrict__ sg,
                          const float* __restrict__ bg, float* __restrict__ out,
                          __half* __restrict__ out_h, int transpose)
{
    __shared__ float red[4];
    int row = blockIdx.x;
    int tid = threadIdx.x;
    const float* x = in + (size_t)row * D_;
    float v[4];
#pragma unroll
    for (int i = 0; i < 4; i++) v[i] = x[tid + i * 128];
    float s = v[0] + v[1] + v[2] + v[3];
#pragma unroll
    for (int o = 16; o; o >>= 1) s += __shfl_xor_sync(0xffffffffu, s, o);
    if ((tid & 31) == 0) red[tid >> 5] = s;
    __syncthreads();
    float mean = (red[0] + red[1] + red[2] + red[3]) * (1.0f / D_);
    __syncthreads();
    float qv = 0.f;
#pragma unroll
    for (int i = 0; i < 4; i++) { float d = v[i] - mean; qv += d * d; }
#pragma unroll
    for (int o = 16; o; o >>= 1) qv += __shfl_xor_sync(0xffffffffu, qv, o);
    if ((tid & 31) == 0) red[tid >> 5] = qv;
    __syncthreads();
    float var = (red[0] + red[1] + red[2] + red[3]) * (1.0f / D_);
    float inv = rsqrtf(var + 1e-5f);
    int orow = row;
    if (transpose) { int b = row / T_; int t = row - b * T_; orow = t * B_ + b; }
    float* op = out + (size_t)orow * D_;
    __half* oph = out_h ? out_h + (size_t)orow * D_ : nullptr;
#pragma unroll
    for (int i = 0; i < 4; i++) {
        int d = tid + i * 128;
        float val = (v[i] - mean) * inv * sg[d] + bg[d];
        op[d] = val;
        if (oph) oph[d] = __float2half_rn(val);
    }
}

// ---------------- weight float -> half pass ----------------
struct CvtJob { const float* src; __half* dst; int n; };
struct CvtParams { CvtJob j[9]; };
__global__ void cvt_weights(CvtParams p)
{
    const CvtJob J = p.j[blockIdx.y];
    int i = (blockIdx.x * 256 + threadIdx.x) * 4;
    if (i < J.n) {
        float4 v = *(const float4*)(J.src + i);
        __half2* d = (__half2*)(J.dst + i);
        d[0] = __floats2half2_rn(v.x, v.y);
        d[1] = __floats2half2_rn(v.z, v.w);
    }
}

// ---------------- launch ----------------
extern "C" void kernel_launch(void* const* d_in, const int* in_sizes, int n_in,
                              void* d_out, int out_size)
{
    const float* tgt       = (const float*)d_in[0];
    const float* em        = (const float*)d_in[1];
    const unsigned char* pad = (const unsigned char*)d_in[2];
    const float* memory    = (const float*)d_in[3];
    const float* sa_q_w    = (const float*)d_in[4];
    const float* sa_q_b    = (const float*)d_in[5];
    const float* sa_k_w    = (const float*)d_in[6];
    const float* sa_k_b    = (const float*)d_in[7];
    const float* sa_v_w    = (const float*)d_in[8];
    const float* sa_v_b    = (const float*)d_in[9];
    const float* sa_rel    = (const float*)d_in[10];
    const float* sa_out_w  = (const float*)d_in[11];
    const float* sa_out_b  = (const float*)d_in[12];
    const float* ca_in_w   = (const float*)d_in[13];
    const float* ca_in_b   = (const float*)d_in[14];
    const float* ca_out_w  = (const float*)d_in[15];
    const float* ca_out_b  = (const float*)d_in[16];
    const float* lin1_w    = (const float*)d_in[17];
    const float* lin1_b    = (const float*)d_in[18];
    const float* lin2_w    = (const float*)d_in[19];
    const float* lin2_b    = (const float*)d_in[20];
    const float* ln1_s     = (const float*)d_in[21];
    const float* ln1_b     = (const float*)d_in[22];
    const float* ln2_s     = (const float*)d_in[23];
    const float* ln2_b     = (const float*)d_in[24];
    const float* ln3_s     = (const float*)d_in[25];
    const float* ln3_b     = (const float*)d_in[26];

    float *x, *sc, *tmp, *x1, *x2;
    __half *xh, *memh, *qh, *kh, *vth, *qlh, *sch, *oh, *x1h, *x2h, *ffnh, *wh;
    cudaGetSymbolAddress((void**)&x,    g_x);
    cudaGetSymbolAddress((void**)&xh,   g_xh);
    cudaGetSymbolAddress((void**)&memh, g_memh);
    cudaGetSymbolAddress((void**)&qh,   g_qh);
    cudaGetSymbolAddress((void**)&kh,   g_kh);
    cudaGetSymbolAddress((void**)&vth,  g_vth);
    cudaGetSymbolAddress((void**)&qlh,  g_qlh);
    cudaGetSymbolAddress((void**)&sc,   g_sc);
    cudaGetSymbolAddress((void**)&sch,  g_sch);
    cudaGetSymbolAddress((void**)&oh,   g_oh);
    cudaGetSymbolAddress((void**)&tmp,  g_tmp);
    cudaGetSymbolAddress((void**)&x1,   g_x1);
    cudaGetSymbolAddress((void**)&x1h,  g_x1h);
    cudaGetSymbolAddress((void**)&x2,   g_x2);
    cudaGetSymbolAddress((void**)&x2h,  g_x2h);
    cudaGetSymbolAddress((void**)&ffnh, g_ffnh);
    cudaGetSymbolAddress((void**)&wh,   g_wtsh);

    static int attrDone = 0;
    if (!attrDone) {
        cudaFuncSetAttribute(gemm_jobs, cudaFuncAttributeMaxDynamicSharedMemorySize, SM_J);
        cudaFuncSetAttribute(gemm_batch, cudaFuncAttributeMaxDynamicSharedMemorySize, SM_J);
        cudaFuncSetAttribute(sa_scores_kernel, cudaFuncAttributeMaxDynamicSharedMemorySize, SM_SA);
        cudaFuncSetAttribute(attn_v_kernel, cudaFuncAttributeMaxDynamicSharedMemorySize, SM_AV);
        attrDone = 1;
    }

    CvtParams cp;
    cp.j[0] = { sa_q_w,   wh + WQ_OFF,   D_ * D_ };
    cp.j[1] = { sa_k_w,   wh + WK_OFF,   D_ * D_ };
    cp.j[2] = { sa_v_w,   wh + WV_OFF,   D_ * D_ };
    cp.j[3] = { sa_out_w, wh + WO_OFF,   D_ * D_ };
    cp.j[4] = { ca_in_w,  wh + WCA_OFF,  3 * D_ * D_ };
    cp.j[5] = { ca_out_w, wh + WCAO_OFF, D_ * D_ };
    cp.j[6] = { lin1_w,   wh + WL1_OFF,  F_ * D_ };
    cp.j[7] = { lin2_w,   wh + WL2_OFF,  D_ * F_ };
    cp.j[8] = { sa_rel,   wh + WREL_OFF, L_ * HD_ * HD_ };
    cvt_weights<<<dim3(1024, 9), 256>>>(cp);

    GParams g;
    GBatch gb;

    // --- self-attention ---
    transpose_tb<<<T_ * B_, 128>>>(tgt, x, xh, T_);
    transpose_tb<<<S_ * B_, 128>>>(memory, nullptr, memh, S_);
    // QKV: q,k NT; v as v^T = Wv @ x^T (per-row bias). All jobs: 128 blocks.
    g.j[0] = { xh, wh + WQ_OFF, sa_q_b, nullptr, nullptr, qh, D_, D_, D_, D_, 4, 1, 0 };
    g.j[1] = { xh, wh + WK_OFF, sa_k_b, nullptr, nullptr, kh, D_, D_, D_, D_, 4, 1, 0 };
    g.j[2] = { wh + WV_OFF, xh, sa_v_b, nullptr, nullptr, vth, D_, D_, B_ * T_, D_, 32, 2, 0 };
    gemm_jobs<<<dim3(128, 1, 3), 128, SM_J>>>(g);
    // ql[z][i][l*64+e] = q_z[512x64] @ relstack[512x64]^T, batched over z
    gb = { qh, wh + WREL_OFF, nullptr, qlh,
           (long long)T_ * D_, HD_, 0, 0, 8LL * T_ * (L_ * HD_), (long long)T_ * (L_ * HD_),
           D_, HD_, L_ * HD_, HD_, 4, 1.0f };
    gemm_batch<<<dim3(16, 1, 64), 128, SM_J>>>(gb);
    sa_scores_kernel<<<dim3(T_ / 64, T_ / 128, B_ * H_), 128, SM_SA>>>(qlh, kh, em, pad, sc);
    softmax_kernel<<<B_ * H_ * T_, 256>>>(sc, sch);
    attn_v_kernel<<<dim3(1, T_ / 128, B_ * H_), 128, SM_AV>>>(sch, vth, oh, T_);
    g.j[0] = { oh, wh + WO_OFF, sa_out_b, x, tmp, nullptr, D_, D_, D_, D_, 4, 1, 0 };
    gemm_jobs<<<dim3(128, 1, 1), 128, SM_J>>>(g);
    ln_kernel<<<B_ * T_, 128>>>(tmp, ln1_s, ln1_b, x1, x1h, 0);

    // --- cross-attention ---
    g.j[0] = { x1h,  wh + WCA_OFF,               ca_in_b,          nullptr, nullptr, qh,  D_, D_, D_, D_, 4, 1, 0 };
    g.j[1] = { memh, wh + WCA_OFF + D_ * D_,     ca_in_b + D_,     nullptr, nullptr, kh,  D_, D_, D_, D_, 4, 1, 0 };
    g.j[2] = { wh + WCA_OFF + 2 * D_ * D_, memh, ca_in_b + 2 * D_, nullptr, nullptr, vth, D_, D_, B_ * S_, D_, 32, 2, 0 };
    gemm_jobs<<<dim3(128, 1, 3), 128, SM_J>>>(g);
    // cross scores: per z, [512x512x64], scale 0.125, fp32 out
    gb = { qh, kh, sc, nullptr,
           (long long)T_ * D_, HD_, (long long)S_ * D_, HD_,
           8LL * T_ * S_, (long long)T_ * S_,
           D_, D_, S_, HD_, 4, 0.125f };
    gemm_batch<<<dim3(16, 1, 64), 128, SM_J>>>(gb);
    softmax_kernel<<<B_ * H_ * T_, 256>>>(sc, sch);
    attn_v_kernel<<<dim3(1, T_ / 128, B_ * H_), 128, SM_AV>>>(sch, vth, oh, S_);
    g.j[0] = { oh, wh + WCAO_OFF, ca_out_b, x1, tmp, nullptr, D_, D_, D_, D_, 4, 1, 0 };
    gemm_jobs<<<dim3(128, 1, 1), 128, SM_J>>>(g);
    ln_kernel<<<B_ * T_, 128>>>(tmp, ln2_s, ln2_b, x2, x2h, 0);

    // --- FFN ---
    g.j[0] = { x2h, wh + WL1_OFF, lin1_b, nullptr, nullptr, ffnh, D_, D_, F_, D_, 16, 1, 1 };
    gemm_jobs<<<dim3(512, 1, 1), 128, SM_J>>>(g);
    g.j[0] = { ffnh, wh + WL2_OFF, lin2_b, x2, tmp, nullptr, F_, F_, D_, F_, 4, 1, 0 };
    gemm_jobs<<<dim3(128, 1, 1), 128, SM_J>>>(g);
    ln_kernel<<<B_ * T_, 128>>>(tmp, ln3_s, ln3_b, (float*)d_out, nullptr, 1);
}

// round 16
// speedup vs baseline: 1.0868x; 1.0868x over previous
#include <cuda_runtime.h>
#include <cuda_fp16.h>

#define T_ 512
#define S_ 512
#define B_ 8
#define D_ 512
#define H_ 8
#define HD_ 64
#define L_ 8
#define F_ 2048

// ---------------- scratch (device globals; no runtime allocation) ----------------
__device__ float  g_x  [B_*T_*D_];      // raw tgt (B,T,D) for residual
__device__ __half g_xh [B_*T_*D_];
__device__ __half g_memh[B_*S_*D_];
__device__ __half g_qh [B_*T_*D_];
__device__ __half g_kh [B_*S_*D_];
__device__ __half g_vth[D_*B_*S_];      // v^T : [channel][b*S+j]
__device__ __half g_qlh[B_*H_*T_*(L_*HD_)];   // [z=bh][i][l*64+e]
__device__ float  g_sc [B_*H_*T_*T_];
__device__ __half g_sch[B_*H_*T_*T_];
__device__ __half g_oh [B_*T_*D_];
__device__ float  g_tmp[B_*T_*D_];
__device__ float  g_x1 [B_*T_*D_];
__device__ __half g_x1h[B_*T_*D_];
__device__ float  g_x2 [B_*T_*D_];
__device__ __half g_x2h[B_*T_*D_];
__device__ __half g_ffnh[B_*T_*F_];
__device__ __half g_wtsh[4227072];

#define WQ_OFF   0
#define WK_OFF   262144
#define WV_OFF   524288
#define WO_OFF   786432
#define WCA_OFF  1048576
#define WCAO_OFF 1835008
#define WL1_OFF  2097152
#define WL2_OFF  3145728
#define WREL_OFF 4194304

// ---------------- cp.async helpers ----------------
__device__ __forceinline__ void cp16(unsigned dst, const void* src) {
    asm volatile("cp.async.ca.shared.global [%0], [%1], 16;" :: "r"(dst), "l"(src));
}
#define CP_COMMIT() asm volatile("cp.async.commit_group;" ::: "memory")
#define CP_WAIT0()  asm volatile("cp.async.wait_group 0;" ::: "memory")
#define CP_WAIT1()  asm volatile("cp.async.wait_group 1;" ::: "memory")

// K-chunk = 32 halves; row stride 48 halves (96B) -> conflict-free LDS.64
#define TST 48
#define TROW_B 96
#define TB128 (128*TST*2)   // 12288
#define TB64  (64*TST*2)    // 6144
#define SM_J  (3*(TB128+TB128))   // 73728
#define SM_SA (2*TB128+2*TB64)    // 36864
#define SM_AV (3*(TB128+TB64))    // 55296

// stage a ROWSx32-half tile with NT threads
template<int ROWS, int NT>
__device__ __forceinline__ void cpT(unsigned dst, const __half* __restrict__ src,
                                    int ld, int k0, int tid)
{
#pragma unroll
    for (int i = 0; i < (ROWS * 4) / NT; i++) {
        int idx = tid + i * NT;
        int row = idx >> 2, seg = idx & 3;
        cp16(dst + row * TROW_B + seg * 16, src + (size_t)row * ld + k0 + seg * 8);
    }
}

// ---------------- fp16 mma warp tile: (MF*16) x (NF*8), one K=32 chunk ----------------
__device__ __forceinline__ void mma16(float* c, const unsigned* a, const unsigned* b) {
    asm volatile(
        "mma.sync.aligned.m16n8k16.row.col.f32.f16.f16.f32 "
        "{%0,%1,%2,%3}, {%4,%5,%6,%7}, {%8,%9}, {%0,%1,%2,%3};"
        : "+f"(c[0]), "+f"(c[1]), "+f"(c[2]), "+f"(c[3])
        : "r"(a[0]), "r"(a[1]), "r"(a[2]), "r"(a[3]), "r"(b[0]), "r"(b[1]));
}

// k-permuted fragments (same perm on A and B => exact dot product), LDS.64 loads.
template<int MF, int NF>
__device__ __forceinline__ void mma_tile(
    const __half* __restrict__ As, const __half* __restrict__ Ws,
    int warp_m, int warp_n, int lane, float c[MF][NF][4])
{
    int r = lane >> 2, q = lane & 3;
    const __half* Ap = As + (warp_m + r) * TST + 4 * q;
    const __half* Bp = Ws + (warp_n + r) * TST + 4 * q;
#pragma unroll
    for (int kg = 0; kg < 2; kg++) {
        int kb = kg * 16;
        unsigned a[MF][4], b[NF][2];
#pragma unroll
        for (int mf = 0; mf < MF; mf++) {
            uint2 lo = *(const uint2*)(Ap + (mf * 16) * TST + kb);
            uint2 hi = *(const uint2*)(Ap + (mf * 16 + 8) * TST + kb);
            a[mf][0] = lo.x; a[mf][1] = hi.x; a[mf][2] = lo.y; a[mf][3] = hi.y;
        }
#pragma unroll
        for (int nf = 0; nf < NF; nf++) {
            uint2 bb = *(const uint2*)(Bp + nf * 8 * TST + kb);
            b[nf][0] = bb.x; b[nf][1] = bb.y;
        }
#pragma unroll
        for (int mf = 0; mf < MF; mf++)
#pragma unroll
            for (int nf = 0; nf < NF; nf++)
                mma16(c[mf][nf], a[mf], b[nf]);
    }
}

// ---------------- jobs GEMM: CTA 128x128, 8 warps (2Mx4N) of 64x32 ----------------
struct GJob {
    const __half* A; const __half* W;
    const float* bias; const float* res;
    float* Cf; __half* Ch;
    int lda, ldw, ldc, K, gx, biasMode, relu;
};
struct GParams { GJob j[3]; };

__global__ __launch_bounds__(256) void gemm_jobs(GParams g)
{
    extern __shared__ __half sm[];
    __half* As = sm;
    __half* Ws = sm + 3 * 128 * TST;
    const GJob J = g.j[blockIdx.z];
    int tid = threadIdx.x, w = tid >> 5, lane = tid & 31;
    int warp_m = (w >> 2) * 64, warp_n = (w & 3) * 32;
    int bx = blockIdx.x % J.gx, by = blockIdx.x / J.gx;
    int row0 = by * 128, col0 = bx * 128;
    const __half* Ab = J.A + (size_t)row0 * J.lda;
    const __half* Wb = J.W + (size_t)col0 * J.ldw;
    unsigned sA = (unsigned)__cvta_generic_to_shared(As);
    unsigned sW = (unsigned)__cvta_generic_to_shared(Ws);
    float c[4][4][4] = {};
    int nch = J.K >> 5;
#pragma unroll
    for (int s = 0; s < 2; s++) {
        cpT<128, 256>(sA + s * TB128, Ab, J.lda, s << 5, tid);
        cpT<128, 256>(sW + s * TB128, Wb, J.ldw, s << 5, tid);
        CP_COMMIT();
    }
    for (int ch = 0; ch < nch; ch++) {
        if (ch < nch - 1) { CP_WAIT1(); } else { CP_WAIT0(); }
        __syncthreads();
        int nx = ch + 2;
        if (nx < nch) {
            int bs = nx % 3;
            cpT<128, 256>(sA + bs * TB128, Ab, J.lda, nx << 5, tid);
            cpT<128, 256>(sW + bs * TB128, Wb, J.ldw, nx << 5, tid);
            CP_COMMIT();
        }
        mma_tile<4, 4>(As + (ch % 3) * 128 * TST, Ws + (ch % 3) * 128 * TST,
                       warp_m, warp_n, lane, c);
    }
    int r = lane >> 2, q = lane & 3;
#pragma unroll
    for (int mf = 0; mf < 4; mf++)
#pragma unroll
    for (int rr = 0; rr < 2; rr++) {
        int row = row0 + warp_m + mf * 16 + r + rr * 8;
        float rb = (J.biasMode == 2) ? J.bias[row] : 0.f;
#pragma unroll
        for (int nf = 0; nf < 4; nf++) {
            int col = col0 + warp_n + nf * 8 + 2 * q;
            float2 o = make_float2(c[mf][nf][2 * rr], c[mf][nf][2 * rr + 1]);
            if (J.biasMode == 1) {
                float2 bb = *(const float2*)(J.bias + col);
                o.x += bb.x; o.y += bb.y;
            } else if (J.biasMode == 2) { o.x += rb; o.y += rb; }
            if (J.res) {
                float2 rv = *(const float2*)(J.res + (size_t)row * J.ldc + col);
                o.x += rv.x; o.y += rv.y;
            }
            if (J.relu) { o.x = fmaxf(o.x, 0.f); o.y = fmaxf(o.y, 0.f); }
            if (J.Cf) *(float2*)(J.Cf + (size_t)row * J.ldc + col) = o;
            if (J.Ch) *((__half2*)(J.Ch + (size_t)row * J.ldc + col)) =
                          __floats2half2_rn(o.x, o.y);
        }
    }
}

// ---------------- batched GEMM over z: CTA 128x128, warps 2Mx4N of 64x32 ----------------
struct GBatch {
    const __half* A; const __half* W; float* Cf; __half* Ch;
    long long Ahi, Alo, Whi, Wlo, Chi, Clo;
    int lda, ldw, ldc, K, gx; float scale;
};

__global__ __launch_bounds__(256) void gemm_batch(GBatch g)
{
    extern __shared__ __half sm[];
    __half* As = sm;
    __half* Ws = sm + 3 * 128 * TST;
    int tid = threadIdx.x, w = tid >> 5, lane = tid & 31;
    int warp_m = (w >> 2) * 64, warp_n = (w & 3) * 32;
    int bx = blockIdx.x % g.gx, by = blockIdx.x / g.gx;
    int z = blockIdx.z, zhi = z >> 3, zlo = z & 7;
    int row0 = by * 128, col0 = bx * 128;
    const __half* Ab = g.A + zhi * g.Ahi + zlo * g.Alo + (size_t)row0 * g.lda;
    const __half* Wb = g.W + zhi * g.Whi + zlo * g.Wlo + (size_t)col0 * g.ldw;
    unsigned sA = (unsigned)__cvta_generic_to_shared(As);
    unsigned sW = (unsigned)__cvta_generic_to_shared(Ws);
    float c[4][4][4] = {};
    int nch = g.K >> 5;
#pragma unroll
    for (int s = 0; s < 2; s++) {
        if (s < nch) {
            cpT<128, 256>(sA + s * TB128, Ab, g.lda, s << 5, tid);
            cpT<128, 256>(sW + s * TB128, Wb, g.ldw, s << 5, tid);
        }
        CP_COMMIT();
    }
    for (int ch = 0; ch < nch; ch++) {
        if (ch < nch - 1) { CP_WAIT1(); } else { CP_WAIT0(); }
        __syncthreads();
        int nx = ch + 2;
        if (nx < nch) {
            int bs = nx % 3;
            cpT<128, 256>(sA + bs * TB128, Ab, g.lda, nx << 5, tid);
            cpT<128, 256>(sW + bs * TB128, Wb, g.ldw, nx << 5, tid);
            CP_COMMIT();
        }
        mma_tile<4, 4>(As + (ch % 3) * 128 * TST, Ws + (ch % 3) * 128 * TST,
                       warp_m, warp_n, lane, c);
    }
    int r = lane >> 2, q = lane & 3;
    float* Cf = g.Cf ? g.Cf + zhi * g.Chi + zlo * g.Clo : nullptr;
    __half* Ch = g.Ch ? g.Ch + zhi * g.Chi + zlo * g.Clo : nullptr;
#pragma unroll
    for (int mf = 0; mf < 4; mf++)
#pragma unroll
    for (int rr = 0; rr < 2; rr++) {
        int row = row0 + warp_m + mf * 16 + r + rr * 8;
#pragma unroll
        for (int nf = 0; nf < 4; nf++) {
            int col = col0 + warp_n + nf * 8 + 2 * q;
            float2 o = make_float2(c[mf][nf][2 * rr] * g.scale,
                                   c[mf][nf][2 * rr + 1] * g.scale);
            if (Cf) *(float2*)(Cf + (size_t)row * g.ldc + col) = o;
            if (Ch) *((__half2*)(Ch + (size_t)row * g.ldc + col)) =
                        __floats2half2_rn(o.x, o.y);
        }
    }
}

// ---------------- sa scores: CTA 128x64, 8 warps (4Mx2N) of 32x32 (R11 shape) ----------------
__global__ __launch_bounds__(256) void sa_scores_kernel(
    const __half* __restrict__ qlb, const __half* __restrict__ km,
    const float* __restrict__ em, const unsigned char* __restrict__ pad,
    float* __restrict__ sc)
{
    extern __shared__ __half sm[];
    __half* As = sm;
    __half* Ws2 = sm + 2 * 128 * TST;
    int z = blockIdx.z; int h = z & 7, b = z >> 3;
    int i0 = blockIdx.y * 128, j0 = blockIdx.x * 64;
    int tid = threadIdx.x, w = tid >> 5, lane = tid & 31;
    int warp_m = (w >> 1) * 32, warp_n = (w & 1) * 32;
    int r = lane >> 2, q = lane & 3;
    unsigned sA = (unsigned)__cvta_generic_to_shared(As);
    unsigned sW = (unsigned)__cvta_generic_to_shared(Ws2);
    const __half* Kb = km + (size_t)(b * T_ + j0) * D_ + h * HD_;
    const __half* A0 = qlb + ((size_t)z * T_ + i0) * (L_ * HD_);
    cpT<64, 256>(sW, Kb, D_, 0, tid);
    cpT<64, 256>(sW + TB64, Kb, D_, 32, tid);
    cpT<128, 256>(sA, A0, L_ * HD_, 0, tid);
    CP_COMMIT();

    float acc[2][4][4] = {};
    for (int l = 0; l < L_; l++) {
        float c[2][4][4] = {};
#pragma unroll
        for (int kc = 0; kc < 2; kc++) {
            int cc = l * 2 + kc;
            CP_WAIT0();
            __syncthreads();
            if (cc < 15) {
                cpT<128, 256>(sA + ((cc + 1) & 1) * TB128, A0, L_ * HD_, (cc + 1) << 5, tid);
                CP_COMMIT();
            }
            mma_tile<2, 4>(As + (cc & 1) * 128 * TST, Ws2 + kc * 64 * TST,
                           warp_m, warp_n, lane, c);
        }
        const float* emb = em + (size_t)(b * L_ + l) * T_ * T_;
#pragma unroll
        for (int mf = 0; mf < 2; mf++)
#pragma unroll
        for (int rr = 0; rr < 2; rr++) {
            int i = i0 + warp_m + mf * 16 + r + rr * 8;
#pragma unroll
            for (int nf = 0; nf < 4; nf++) {
                int j = j0 + warp_n + nf * 8 + 2 * q;
                float2 e = *(const float2*)(emb + (size_t)i * T_ + j);
                acc[mf][nf][2 * rr]     += e.x * c[mf][nf][2 * rr];
                acc[mf][nf][2 * rr + 1] += e.y * c[mf][nf][2 * rr + 1];
            }
        }
    }
#pragma unroll
    for (int mf = 0; mf < 2; mf++)
#pragma unroll
    for (int rr = 0; rr < 2; rr++) {
        int i = i0 + warp_m + mf * 16 + r + rr * 8;
#pragma unroll
        for (int nf = 0; nf < 4; nf++) {
            int j = j0 + warp_n + nf * 8 + 2 * q;
            const unsigned char* pp = pad + (size_t)(b * T_ + i) * T_ + j;
            float2 o;
            o.x = pp[0] ? -1e9f : acc[mf][nf][2 * rr] * 0.125f;
            o.y = pp[1] ? -1e9f : acc[mf][nf][2 * rr + 1] * 0.125f;
            *(float2*)(sc + ((size_t)z * T_ + i) * T_ + j) = o;
        }
    }
}

// ---------------- row softmax over width 512: float in -> half out ----------------
__global__ void softmax_kernel(const float* __restrict__ sc, __half* __restrict__ sch)
{
    __shared__ float red[8];
    int row = blockIdx.x;
    int tid = threadIdx.x;
    const float* p = sc + (size_t)row * 512;
    __half* ph = sch + (size_t)row * 512;
    float a0 = p[tid], a1 = p[tid + 256];
    float m = fmaxf(a0, a1);
#pragma unroll
    for (int o = 16; o; o >>= 1) m = fmaxf(m, __shfl_xor_sync(0xffffffffu, m, o));
    if ((tid & 31) == 0) red[tid >> 5] = m;
    __syncthreads();
    m = red[0];
#pragma unroll
    for (int i = 1; i < 8; i++) m = fmaxf(m, red[i]);
    float e0 = __expf(a0 - m), e1 = __expf(a1 - m);
    float s = e0 + e1;
#pragma unroll
    for (int o = 16; o; o >>= 1) s += __shfl_xor_sync(0xffffffffu, s, o);
    __syncthreads();
    if ((tid & 31) == 0) red[tid >> 5] = s;
    __syncthreads();
    s = red[0] + red[1] + red[2] + red[3] + red[4] + red[5] + red[6] + red[7];
    float inv = 1.0f / s;
    ph[tid] = __float2half_rn(e0 * inv);
    ph[tid + 256] = __float2half_rn(e1 * inv);
}

// ---------------- o = attn @ v via NT with v^T: CTA 128x64, warps 4Mx2N (R11 shape) ----------------
__global__ __launch_bounds__(256) void attn_v_kernel(
    const __half* __restrict__ attn, const __half* __restrict__ vt,
    __half* __restrict__ o, int kdim)
{
    extern __shared__ __half sm[];
    __half* As = sm;
    __half* Ws = sm + 3 * 128 * TST;
    int z = blockIdx.z; int h = z & 7, b = z >> 3;
    int i0 = blockIdx.y * 128;
    int tid = threadIdx.x, w = tid >> 5, lane = tid & 31;
    int warp_m = (w >> 1) * 32, warp_n = (w & 1) * 32;
    const __half* Ab = attn + (size_t)z * T_ * kdim + (size_t)i0 * kdim;
    const __half* Wb = vt + (size_t)(h * HD_) * (B_ * kdim) + (size_t)b * kdim;
    int ldw = B_ * kdim;
    unsigned sA = (unsigned)__cvta_generic_to_shared(As);
    unsigned sW = (unsigned)__cvta_generic_to_shared(Ws);
    float c[2][4][4] = {};
    int nch = kdim >> 5;
#pragma unroll
    for (int s = 0; s < 2; s++) {
        cpT<128, 256>(sA + s * TB128, Ab, kdim, s << 5, tid);
        cpT<64, 256>(sW + s * TB64, Wb, ldw, s << 5, tid);
        CP_COMMIT();
    }
    for (int ch = 0; ch < nch; ch++) {
        if (ch < nch - 1) { CP_WAIT1(); } else { CP_WAIT0(); }
        __syncthreads();
        int nx = ch + 2;
        if (nx < nch) {
            int bs = nx % 3;
            cpT<128, 256>(sA + bs * TB128, Ab, kdim, nx << 5, tid);
            cpT<64, 256>(sW + bs * TB64, Wb, ldw, nx << 5, tid);
            CP_COMMIT();
        }
        mma_tile<2, 4>(As + (ch % 3) * 128 * TST, Ws + (ch % 3) * 64 * TST,
                       warp_m, warp_n, lane, c);
    }
    int r = lane >> 2, q = lane & 3;
    __half* Ob = o + (size_t)(b * T_ + i0) * D_ + h * HD_;
#pragma unroll
    for (int mf = 0; mf < 2; mf++)
#pragma unroll
    for (int rr = 0; rr < 2; rr++) {
        int row = warp_m + mf * 16 + r + rr * 8;
#pragma unroll
        for (int nf = 0; nf < 4; nf++) {
            int col = warp_n + nf * 8 + 2 * q;
            *((__half2*)(Ob + (size_t)row * D_ + col)) =
                __floats2half2_rn(c[mf][nf][2 * rr], c[mf][nf][2 * rr + 1]);
        }
    }
}

// ---------------- (T,B,D) -> (B,T,D) gather; raw float (optional) + half ----------------
__global__ void transpose_tb(const float* __restrict__ in, float* __restrict__ out_raw,
                             __half* __restrict__ out_h, int Tdim)
{
    int row = blockIdx.x;
    int t = row / B_, b = row - t * B_;
    float4 v = ((const float4*)(in + (size_t)(t * B_ + b) * D_))[threadIdx.x];
    size_t off = (size_t)(b * Tdim + t) * D_;
    if (out_raw) ((float4*)(out_raw + off))[threadIdx.x] = v;
    __half2* hp = (__half2*)(out_h + off + threadIdx.x * 4);
    hp[0] = __floats2half2_rn(v.x, v.y);
    hp[1] = __floats2half2_rn(v.z, v.w);
}

// ---------------- LayerNorm over D=512; raw float + optional half ----------------
__global__ void ln_kernel(const float* __restrict__ in, const float* __restrict__ sg,
                          const float* __restrict__ bg, float* __restrict__ out,
                          __half* __restrict__ out_h, int transpose)
{
    __shared__ float red[4];
    int row = blockIdx.x;
    int tid = threadIdx.x;
    const float* x = in + (size_t)row * D_;
    float v[4];
#pragma unroll
    for (int i = 0; i < 4; i++) v[i] = x[tid + i * 128];
    float s = v[0] + v[1] + v[2] + v[3];
#pragma unroll
    for (int o = 16; o; o >>= 1) s += __shfl_xor_sync(0xffffffffu, s, o);
    if ((tid & 31) == 0) red[tid >> 5] = s;
    __syncthreads();
    float mean = (red[0] + red[1] + red[2] + red[3]) * (1.0f / D_);
    __syncthreads();
    float qv = 0.f;
#pragma unroll
    for (int i = 0; i < 4; i++) { float d = v[i] - mean; qv += d * d; }
#pragma unroll
    for (int o = 16; o; o >>= 1) qv += __shfl_xor_sync(0xffffffffu, qv, o);
    if ((tid & 31) == 0) red[tid >> 5] = qv;
    __syncthreads();
    float var = (red[0] + red[1] + red[2] + red[3]) * (1.0f / D_);
    float inv = rsqrtf(var + 1e-5f);
    int orow = row;
    if (transpose) { int b = row / T_; int t = row - b * T_; orow = t * B_ + b; }
    float* op = out + (size_t)orow * D_;
    __half* oph = out_h ? out_h + (size_t)orow * D_ : nullptr;
#pragma unroll
    for (int i = 0; i < 4; i++) {
        int d = tid + i * 128;
        float val = (v[i] - mean) * inv * sg[d] + bg[d];
        op[d] = val;
        if (oph) oph[d] = __float2half_rn(val);
    }
}

// ---------------- weight float -> half pass ----------------
struct CvtJob { const float* src; __half* dst; int n; };
struct CvtParams { CvtJob j[9]; };
__global__ void cvt_weights(CvtParams p)
{
    const CvtJob J = p.j[blockIdx.y];
    int i = (blockIdx.x * 256 + threadIdx.x) * 4;
    if (i < J.n) {
        float4 v = *(const float4*)(J.src + i);
        __half2* d = (__half2*)(J.dst + i);
        d[0] = __floats2half2_rn(v.x, v.y);
        d[1] = __floats2half2_rn(v.z, v.w);
    }
}

// ---------------- launch ----------------
extern "C" void kernel_launch(void* const* d_in, const int* in_sizes, int n_in,
                              void* d_out, int out_size)
{
    const float* tgt       = (const float*)d_in[0];
    const float* em        = (const float*)d_in[1];
    const unsigned char* pad = (const unsigned char*)d_in[2];
    const float* memory    = (const float*)d_in[3];
    const float* sa_q_w    = (const float*)d_in[4];
    const float* sa_q_b    = (const float*)d_in[5];
    const float* sa_k_w    = (const float*)d_in[6];
    const float* sa_k_b    = (const float*)d_in[7];
    const float* sa_v_w    = (const float*)d_in[8];
    const float* sa_v_b    = (const float*)d_in[9];
    const float* sa_rel    = (const float*)d_in[10];
    const float* sa_out_w  = (const float*)d_in[11];
    const float* sa_out_b  = (const float*)d_in[12];
    const float* ca_in_w   = (const float*)d_in[13];
    const float* ca_in_b   = (const float*)d_in[14];
    const float* ca_out_w  = (const float*)d_in[15];
    const float* ca_out_b  = (const float*)d_in[16];
    const float* lin1_w    = (const float*)d_in[17];
    const float* lin1_b    = (const float*)d_in[18];
    const float* lin2_w    = (const float*)d_in[19];
    const float* lin2_b    = (const float*)d_in[20];
    const float* ln1_s     = (const float*)d_in[21];
    const float* ln1_b     = (const float*)d_in[22];
    const float* ln2_s     = (const float*)d_in[23];
    const float* ln2_b     = (const float*)d_in[24];
    const float* ln3_s     = (const float*)d_in[25];
    const float* ln3_b     = (const float*)d_in[26];

    float *x, *sc, *tmp, *x1, *x2;
    __half *xh, *memh, *qh, *kh, *vth, *qlh, *sch, *oh, *x1h, *x2h, *ffnh, *wh;
    cudaGetSymbolAddress((void**)&x,    g_x);
    cudaGetSymbolAddress((void**)&xh,   g_xh);
    cudaGetSymbolAddress((void**)&memh, g_memh);
    cudaGetSymbolAddress((void**)&qh,   g_qh);
    cudaGetSymbolAddress((void**)&kh,   g_kh);
    cudaGetSymbolAddress((void**)&vth,  g_vth);
    cudaGetSymbolAddress((void**)&qlh,  g_qlh);
    cudaGetSymbolAddress((void**)&sc,   g_sc);
    cudaGetSymbolAddress((void**)&sch,  g_sch);
    cudaGetSymbolAddress((void**)&oh,   g_oh);
    cudaGetSymbolAddress((void**)&tmp,  g_tmp);
    cudaGetSymbolAddress((void**)&x1,   g_x1);
    cudaGetSymbolAddress((void**)&x1h,  g_x1h);
    cudaGetSymbolAddress((void**)&x2,   g_x2);
    cudaGetSymbolAddress((void**)&x2h,  g_x2h);
    cudaGetSymbolAddress((void**)&ffnh, g_ffnh);
    cudaGetSymbolAddress((void**)&wh,   g_wtsh);

    static int attrDone = 0;
    if (!attrDone) {
        cudaFuncSetAttribute(gemm_jobs, cudaFuncAttributeMaxDynamicSharedMemorySize, SM_J);
        cudaFuncSetAttribute(gemm_batch, cudaFuncAttributeMaxDynamicSharedMemorySize, SM_J);
        cudaFuncSetAttribute(sa_scores_kernel, cudaFuncAttributeMaxDynamicSharedMemorySize, SM_SA);
        cudaFuncSetAttribute(attn_v_kernel, cudaFuncAttributeMaxDynamicSharedMemorySize, SM_AV);
        attrDone = 1;
    }

    CvtParams cp;
    cp.j[0] = { sa_q_w,   wh + WQ_OFF,   D_ * D_ };
    cp.j[1] = { sa_k_w,   wh + WK_OFF,   D_ * D_ };
    cp.j[2] = { sa_v_w,   wh + WV_OFF,   D_ * D_ };
    cp.j[3] = { sa_out_w, wh + WO_OFF,   D_ * D_ };
    cp.j[4] = { ca_in_w,  wh + WCA_OFF,  3 * D_ * D_ };
    cp.j[5] = { ca_out_w, wh + WCAO_OFF, D_ * D_ };
    cp.j[6] = { lin1_w,   wh + WL1_OFF,  F_ * D_ };
    cp.j[7] = { lin2_w,   wh + WL2_OFF,  D_ * F_ };
    cp.j[8] = { sa_rel,   wh + WREL_OFF, L_ * HD_ * HD_ };
    cvt_weights<<<dim3(1024, 9), 256>>>(cp);

    GParams g;
    GBatch gb;

    // --- self-attention ---
    transpose_tb<<<T_ * B_, 128>>>(tgt, x, xh, T_);
    transpose_tb<<<S_ * B_, 128>>>(memory, nullptr, memh, S_);
    // QKV: q,k NT; v as v^T = Wv @ x^T (per-row bias). 128 blocks per job.
    g.j[0] = { xh, wh + WQ_OFF, sa_q_b, nullptr, nullptr, qh, D_, D_, D_, D_, 4, 1, 0 };
    g.j[1] = { xh, wh + WK_OFF, sa_k_b, nullptr, nullptr, kh, D_, D_, D_, D_, 4, 1, 0 };
    g.j[2] = { wh + WV_OFF, xh, sa_v_b, nullptr, nullptr, vth, D_, D_, B_ * T_, D_, 32, 2, 0 };
    gemm_jobs<<<dim3(128, 1, 3), 256, SM_J>>>(g);
    // ql[z][i][l*64+e] = q_z[512x64] @ relstack[512x64]^T, batched over z
    gb = { qh, wh + WREL_OFF, nullptr, qlh,
           (long long)T_ * D_, HD_, 0, 0, 8LL * T_ * (L_ * HD_), (long long)T_ * (L_ * HD_),
           D_, HD_, L_ * HD_, HD_, 4, 1.0f };
    gemm_batch<<<dim3(16, 1, 64), 256, SM_J>>>(gb);
    sa_scores_kernel<<<dim3(T_ / 64, T_ / 128, B_ * H_), 256, SM_SA>>>(qlh, kh, em, pad, sc);
    softmax_kernel<<<B_ * H_ * T_, 256>>>(sc, sch);
    attn_v_kernel<<<dim3(1, T_ / 128, B_ * H_), 256, SM_AV>>>(sch, vth, oh, T_);
    g.j[0] = { oh, wh + WO_OFF, sa_out_b, x, tmp, nullptr, D_, D_, D_, D_, 4, 1, 0 };
    gemm_jobs<<<dim3(128, 1, 1), 256, SM_J>>>(g);
    ln_kernel<<<B_ * T_, 128>>>(tmp, ln1_s, ln1_b, x1, x1h, 0);

    // --- cross-attention ---
    g.j[0] = { x1h,  wh + WCA_OFF,               ca_in_b,          nullptr, nullptr, qh,  D_, D_, D_, D_, 4, 1, 0 };
    g.j[1] = { memh, wh + WCA_OFF + D_ * D_,     ca_in_b + D_,     nullptr, nullptr, kh,  D_, D_, D_, D_, 4, 1, 0 };
    g.j[2] = { wh + WCA_OFF + 2 * D_ * D_, memh, ca_in_b + 2 * D_, nullptr, nullptr, vth, D_, D_, B_ * S_, D_, 32, 2, 0 };
    gemm_jobs<<<dim3(128, 1, 3), 256, SM_J>>>(g);
    // cross scores: per z, [512x512x64], scale 0.125, fp32 out
    gb = { qh, kh, sc, nullptr,
           (long long)T_ * D_, HD_, (long long)S_ * D_, HD_,
           8LL * T_ * S_, (long long)T_ * S_,
           D_, D_, S_, HD_, 4, 0.125f };
    gemm_batch<<<dim3(16, 1, 64), 256, SM_J>>>(gb);
    softmax_kernel<<<B_ * H_ * T_, 256>>>(sc, sch);
    attn_v_kernel<<<dim3(1, T_ / 128, B_ * H_), 256, SM_AV>>>(sch, vth, oh, S_);
    g.j[0] = { oh, wh + WCAO_OFF, ca_out_b, x1, tmp, nullptr, D_, D_, D_, D_, 4, 1, 0 };
    gemm_jobs<<<dim3(128, 1, 1), 256, SM_J>>>(g);
    ln_kernel<<<B_ * T_, 128>>>(tmp, ln2_s, ln2_b, x2, x2h, 0);

    // --- FFN ---
    g.j[0] = { x2h, wh + WL1_OFF, lin1_b, nullptr, nullptr, ffnh, D_, D_, F_, D_, 16, 1, 1 };
    gemm_jobs<<<dim3(512, 1, 1), 256, SM_J>>>(g);
    g.j[0] = { ffnh, wh + WL2_OFF, lin2_b, x2, tmp, nullptr, F_, F_, D_, F_, 4, 1, 0 };
    gemm_jobs<<<dim3(128, 1, 1), 256, SM_J>>>(g);
    ln_kernel<<<B_ * T_, 128>>>(tmp, ln3_s, ln3_b, (float*)d_out, nullptr, 1);
}